// round 13
// baseline (speedup 1.0000x reference)
#include <cuda_runtime.h>
#include <cuda_bf16.h>
#include <cuda_fp16.h>
#include <cstdint>

// ---------------- problem constants ----------------
#define NP 100000
#define NL 80000
#define NG 50000
#define EDG 400000
#define DIN 512
#define DOUT 128
#define TOTROWS 690000
#define XROWS 230000
#define BCAP 64

// host-side relation tables
static const int SRC_T[9] = {0,0,0,1,1,1,2,2,2};
static const int NTY[3]   = {NP, NL, NG};
static const int XOFF3[3] = {0, NP, NP+NL};
static const int SOFF[9]  = {0,100000,200000,300000,380000,460000,540000,590000,640000};

// device-side relation tables
__constant__ int c_soff[9] = {0,100000,200000,300000,380000,460000,540000,590000,640000};
__constant__ int c_doff[9] = {0,100000,180000,230000,310000,410000,460000,510000,610000};
__constant__ int c_rel3[3][3] = {{0,4,7},{1,3,8},{2,5,6}};   // relations targeting type p/l/g

struct EdgePtrs { const int* ei[9]; };

// ---------------- device scratch ----------------
__device__ __half   g_H[(size_t)TOTROWS * DOUT];    // fp16 projected features (176 MB)
__device__ __half   g_Xf[(size_t)XROWS * DIN];      // fp16 X (235 MB)
__device__ __half   g_Wt[9 * DOUT * DIN];           // W^T fp16  [r][n][k]
__device__ float    g_ssrc[TOTROWS];
__device__ float    g_sdst[TOTROWS];
__device__ int      g_cnt[TOTROWS];                 // bucket cursors
__device__ uint2    g_ent[(size_t)TOTROWS * BCAP];  // {src, exp_bits} buckets
__device__ float    g_wv[9 * 2 * DIN];

// ---------------- helpers ----------------
__device__ __forceinline__ uint32_t smem_u32(const void* p) {
    uint32_t a;
    asm("{ .reg .u64 t; cvta.to.shared.u64 t, %1; cvt.u32.u64 %0, t; }" : "=r"(a) : "l"(p));
    return a;
}
__device__ __forceinline__ void cp_async16(uint32_t sdst, const void* gsrc) {
    asm volatile("cp.async.cg.shared.global [%0], [%1], 16;" :: "r"(sdst), "l"(gsrc) : "memory");
}
__device__ __forceinline__ void ldm_x4(uint32_t* r, uint32_t addr) {
    asm volatile("ldmatrix.sync.aligned.m8n8.x4.shared.b16 {%0,%1,%2,%3}, [%4];"
                 : "=r"(r[0]), "=r"(r[1]), "=r"(r[2]), "=r"(r[3]) : "r"(addr));
}
__device__ __forceinline__ void mma16816h(float* d, const uint32_t* a, const uint32_t* b) {
    asm volatile("mma.sync.aligned.m16n8k16.row.col.f32.f16.f16.f32 "
                 "{%0,%1,%2,%3},{%4,%5,%6,%7},{%8,%9},{%0,%1,%2,%3};"
                 : "+f"(d[0]), "+f"(d[1]), "+f"(d[2]), "+f"(d[3])
                 : "r"(a[0]), "r"(a[1]), "r"(a[2]), "r"(a[3]), "r"(b[0]), "r"(b[1]));
}

// ---------------- K0: zero bucket cursors ----------------
__global__ void k_zero_cnt() {
    int i = blockIdx.x * blockDim.x + threadIdx.x;
    if (i < TOTROWS) g_cnt[i] = 0;
}

// ---------------- K1: convert X -> fp16 ----------------
__global__ void k_cvt_x(const float4* __restrict__ x, int n4, long long off4) {
    int i = blockIdx.x * blockDim.x + threadIdx.x;
    if (i >= n4) return;
    float4 v = x[i];
    __half2 h01 = __floats2half2_rn(v.x, v.y);
    __half2 h23 = __floats2half2_rn(v.z, v.w);
    __half2* p = (__half2*)(g_Xf + (size_t)(off4 + i) * 4);
    p[0] = h01; p[1] = h23;
}

// ---------------- K1b: W -> transposed fp16 ----------------
__global__ void k_cvt_w(const float* __restrict__ W) {
    int idx = blockIdx.x * blockDim.x + threadIdx.x;
    if (idx >= 9 * DIN * DOUT) return;
    int r = idx >> 16;
    int k = (idx >> 7) & 511;
    int n = idx & 127;
    g_Wt[(r << 16) + n * DIN + k] = __float2half_rn(W[idx]);
}

// ---------------- K2: wv[r][role] = W[r] @ a  (fp32, exact) ----------------
__global__ void k_wv(const float* __restrict__ W, const float* __restrict__ as_,
                     const float* __restrict__ ad_) {
    int idx = blockIdx.x * blockDim.x + threadIdx.x;
    if (idx >= 9 * 2 * DIN) return;
    int k = idx & (DIN - 1);
    int rr = idx >> 9;
    int role = rr & 1;
    int r = rr >> 1;
    const float* a = (role ? ad_ : as_) + r * DOUT;
    const float* w = W + (size_t)r * DIN * DOUT + (size_t)k * DOUT;
    float s = 0.f;
    #pragma unroll 8
    for (int j = 0; j < DOUT; j++) s = fmaf(w[j], a[j], s);
    g_wv[r * 1024 + role * DIN + k] = s;
}

// ---------------- K3: per-node attention logit halves (fp16 X) ----------------
__device__ __forceinline__ float dot8h(uint4 u, float4 a0, float4 a1) {
    float2 p; float s = 0.f;
    p = __half22float2(*(__half2*)&u.x); s = fmaf(p.x, a0.x, s); s = fmaf(p.y, a0.y, s);
    p = __half22float2(*(__half2*)&u.y); s = fmaf(p.x, a0.z, s); s = fmaf(p.y, a0.w, s);
    p = __half22float2(*(__half2*)&u.z); s = fmaf(p.x, a1.x, s); s = fmaf(p.y, a1.y, s);
    p = __half22float2(*(__half2*)&u.w); s = fmaf(p.x, a1.z, s); s = fmaf(p.y, a1.w, s);
    return s;
}
__device__ __forceinline__ float warp_dot512h(uint4 u0, uint4 u1, const float* v, int lane) {
    const float4* vv = (const float4*)v;
    float s = dot8h(u0, vv[lane * 2],        vv[lane * 2 + 1])
            + dot8h(u1, vv[(lane + 32) * 2], vv[(lane + 32) * 2 + 1]);
    #pragma unroll
    for (int o = 16; o; o >>= 1) s += __shfl_xor_sync(0xffffffffu, s, o);
    return s;
}
__global__ void k_node_dots(int xoff, int n,
                            int r0, int r1, int r2, int so0, int so1, int so2,
                            int d0, int d1, int d2, int q0, int q1, int q2) {
    int gw   = (blockIdx.x * blockDim.x + threadIdx.x) >> 5;
    int lane = threadIdx.x & 31;
    if (gw >= n) return;
    const uint4* xr = (const uint4*)(g_Xf + (size_t)(xoff + gw) * DIN);
    uint4 u0 = xr[lane], u1 = xr[lane + 32];
    float s;
    s = warp_dot512h(u0, u1, g_wv + r0 * 1024,       lane); if (!lane) g_ssrc[so0 + gw] = s;
    s = warp_dot512h(u0, u1, g_wv + r1 * 1024,       lane); if (!lane) g_ssrc[so1 + gw] = s;
    s = warp_dot512h(u0, u1, g_wv + r2 * 1024,       lane); if (!lane) g_ssrc[so2 + gw] = s;
    s = warp_dot512h(u0, u1, g_wv + d0 * 1024 + DIN, lane); if (!lane) g_sdst[q0 + gw] = s;
    s = warp_dot512h(u0, u1, g_wv + d1 * 1024 + DIN, lane); if (!lane) g_sdst[q1 + gw] = s;
    s = warp_dot512h(u0, u1, g_wv + d2 * 1024 + DIN, lane); if (!lane) g_sdst[q2 + gw] = s;
}

// ---------------- K4: fp16 single-product mma.sync GEMM ----------------
// Stage: A(10240) + B(10240) = 20480B; 2 stages = 40960B.
#define GST   20480
#define GROWB 80
#define GE_SMEM (2 * GST)

__global__ __launch_bounds__(256, 2)
void k_mma_gemm(int rowoff, int M, int rel, int hoff) {
    extern __shared__ __align__(128) char smem[];
    uint32_t sb = smem_u32(smem);
    int tid  = threadIdx.x;
    int lane = tid & 31;
    int warp = tid >> 5;
    int wm = warp & 1;
    int wn = warp >> 1;
    int tile0 = blockIdx.x * 128;

    const __half* baseA = g_Xf + (size_t)rowoff * DIN;
    const __half* baseB = g_Wt + ((size_t)rel << 16);

    float acc[4][4][4];
    #pragma unroll
    for (int i = 0; i < 4; i++)
        #pragma unroll
        for (int j = 0; j < 4; j++)
            #pragma unroll
            for (int q = 0; q < 4; q++) acc[i][j][q] = 0.f;

    auto load_chunk = [&](int c) {
        uint32_t stb = sb + (c & 1) * GST;
        int kbase = c * 32;
        #pragma unroll
        for (int t = 0; t < 2; t++) {          // A
            int id  = tid + t * 256;
            int row = id >> 2;
            int c16 = id & 3;
            int grow = tile0 + row; if (grow >= M) grow = M - 1;
            const void* g = baseA + (size_t)grow * DIN + kbase + c16 * 8;
            cp_async16(stb + row * GROWB + c16 * 16, g);
        }
        #pragma unroll
        for (int t = 0; t < 2; t++) {          // B
            int id  = tid + t * 256;
            int row = id >> 2;
            int c16 = id & 3;
            const void* g = baseB + (size_t)row * DIN + kbase + c16 * 8;
            cp_async16(stb + 10240 + row * GROWB + c16 * 16, g);
        }
        asm volatile("cp.async.commit_group;" ::: "memory");
    };

    uint32_t a_off = (uint32_t)(wm * 64 + (lane & 15)) * GROWB + (lane & 16);
    uint32_t b_off = (uint32_t)(wn * 32 + (lane & 7) + ((lane & 16) ? 8 : 0)) * GROWB
                   + ((lane & 8) << 1);

    load_chunk(0);

    for (int c = 0; c < 16; c++) {
        if (c < 15) {
            load_chunk(c + 1);
            asm volatile("cp.async.wait_group 1;" ::: "memory");
        } else {
            asm volatile("cp.async.wait_group 0;" ::: "memory");
        }
        __syncthreads();

        uint32_t stb = sb + (c & 1) * GST;
        uint32_t ah_s = stb;
        uint32_t bh_s = stb + 10240;

        #pragma unroll
        for (int ks = 0; ks < 2; ks++) {
            uint32_t kb = ks * 32;
            uint32_t AH[4][4], B[2][4];
            #pragma unroll
            for (int mf = 0; mf < 4; mf++)
                ldm_x4(AH[mf], ah_s + a_off + mf * (16 * GROWB) + kb);
            #pragma unroll
            for (int g = 0; g < 2; g++)
                ldm_x4(B[g], bh_s + b_off + g * (16 * GROWB) + kb);
            #pragma unroll
            for (int mf = 0; mf < 4; mf++)
                #pragma unroll
                for (int nf = 0; nf < 4; nf++)
                    mma16816h(acc[mf][nf], AH[mf], &B[nf >> 1][(nf & 1) * 2]);
        }
        __syncthreads();
    }

    __half* Cb = g_H + (size_t)hoff * DOUT;
    int r_base = tile0 + wm * 64 + (lane >> 2);
    int c_base = wn * 32 + (lane & 3) * 2;
    #pragma unroll
    for (int mf = 0; mf < 4; mf++) {
        #pragma unroll
        for (int nf = 0; nf < 4; nf++) {
            int r = r_base + mf * 16;
            int cc = c_base + nf * 8;
            if (r < M)
                *(__half2*)(Cb + (size_t)r * DOUT + cc)
                    = __floats2half2_rn(acc[mf][nf][0], acc[mf][nf][1]);
            if (r + 8 < M)
                *(__half2*)(Cb + (size_t)(r + 8) * DOUT + cc)
                    = __floats2half2_rn(acc[mf][nf][2], acc[mf][nf][3]);
        }
    }
}

// ---------------- K5: fill buckets (logit -> exp -> bucket append) ----------------
#define EBPR 1563
__global__ void k_fill(EdgePtrs ep) {
    int rel = blockIdx.x / EBPR;
    int e = (blockIdx.x - rel * EBPR) * 256 + threadIdx.x;
    if (e >= EDG) return;
    const int* ei = ep.ei[rel];
    int s = ei[e], d = ei[EDG + e];
    float a = g_ssrc[c_soff[rel] + s] + g_sdst[c_doff[rel] + d];
    a = (a > 0.f) ? a : 0.2f * a;
    float v = __expf(a);               // logits bounded: max-sub unnecessary
    int slot = c_doff[rel] + d;
    int pos = atomicAdd(&g_cnt[slot], 1);
    if (pos < BCAP)
        g_ent[(size_t)slot * BCAP + pos] = make_uint2((unsigned)s, __float_as_uint(v));
}

// ---------------- K6: per-node accumulation (softmax + gather + mean + bias + relu) ----
__global__ void k_accum(float* __restrict__ out, const float* __restrict__ bias) {
    int gw   = (blockIdx.x * blockDim.x + threadIdx.x) >> 5;
    int lane = threadIdx.x & 31;
    if (gw >= XROWS) return;
    int ty, d;
    if (gw < NP)           { ty = 0; d = gw; }
    else if (gw < NP + NL) { ty = 1; d = gw - NP; }
    else                   { ty = 2; d = gw - NP - NL; }

    float acc0 = 0.f, acc1 = 0.f, acc2 = 0.f, acc3 = 0.f;
    float4 bsum = make_float4(0.f, 0.f, 0.f, 0.f);

    #pragma unroll
    for (int q = 0; q < 3; q++) {
        int r = c_rel3[ty][q];
        float4 bv = *(const float4*)(bias + r * DOUT + lane * 4);
        bsum.x += bv.x; bsum.y += bv.y; bsum.z += bv.z; bsum.w += bv.w;

        int slot = c_doff[r] + d;
        int cnt = g_cnt[slot]; if (cnt > BCAP) cnt = BCAP;
        if (cnt == 0) continue;
        const uint2* lst = g_ent + (size_t)slot * BCAP;
        float den = 0.f;
        for (int j = 0; j < cnt; j++) den += __uint_as_float(lst[j].y);
        float inv = 1.f / den;
        const __half* Hb = g_H + (size_t)c_soff[r] * DOUT;
        for (int j = 0; j < cnt; j++) {
            uint2 en = lst[j];
            float wt = __uint_as_float(en.y) * inv;
            uint2 u = *(const uint2*)(Hb + (size_t)en.x * DOUT + lane * 4);
            float2 f0 = __half22float2(*(__half2*)&u.x);
            float2 f1 = __half22float2(*(__half2*)&u.y);
            acc0 = fmaf(f0.x, wt, acc0);
            acc1 = fmaf(f0.y, wt, acc1);
            acc2 = fmaf(f1.x, wt, acc2);
            acc3 = fmaf(f1.y, wt, acc3);
        }
    }

    float4 o;
    o.x = (acc0 + bsum.x) * (1.0f / 3.0f);
    o.y = (acc1 + bsum.y) * (1.0f / 3.0f);
    o.z = (acc2 + bsum.z) * (1.0f / 3.0f);
    o.w = (acc3 + bsum.w) * (1.0f / 3.0f);
    o.x = o.x > 0.f ? o.x : 0.f;
    o.y = o.y > 0.f ? o.y : 0.f;
    o.z = o.z > 0.f ? o.z : 0.f;
    o.w = o.w > 0.f ? o.w : 0.f;
    *(float4*)(out + (size_t)gw * DOUT + lane * 4) = o;
}

// ---------------- launch ----------------
extern "C" void kernel_launch(void* const* d_in, const int* in_sizes, int n_in,
                              void* d_out, int out_size) {
    const float* X[3] = {(const float*)d_in[0], (const float*)d_in[1], (const float*)d_in[2]};
    EdgePtrs ep;
    for (int r = 0; r < 9; r++) ep.ei[r] = (const int*)d_in[3 + r];
    const float* W    = (const float*)d_in[12];
    const float* as_  = (const float*)d_in[13];
    const float* ad_  = (const float*)d_in[14];
    const float* bias = (const float*)d_in[15];
    float* out = (float*)d_out;

    cudaFuncSetAttribute(k_mma_gemm, cudaFuncAttributeMaxDynamicSharedMemorySize, GE_SMEM);

    // init bucket cursors
    k_zero_cnt<<<(TOTROWS + 255) / 256, 256>>>();

    // conversions
    k_cvt_x<<<(NP * 128 + 255) / 256, 256>>>((const float4*)X[0], NP * 128, 0LL);
    k_cvt_x<<<(NL * 128 + 255) / 256, 256>>>((const float4*)X[1], NL * 128, (long long)NP * 128);
    k_cvt_x<<<(NG * 128 + 255) / 256, 256>>>((const float4*)X[2], NG * 128, (long long)(NP + NL) * 128);
    k_cvt_w<<<(9 * DIN * DOUT + 255) / 256, 256>>>(W);

    // attention-vector precompute + per-node logit halves (reads fp16 X)
    k_wv<<<(9 * 2 * DIN + 255) / 256, 256>>>(W, as_, ad_);
    k_node_dots<<<(NP * 32 + 255) / 256, 256>>>(0, NP, 0, 1, 2, 0, 100000, 200000,
                                                0, 4, 7, 0, 310000, 510000);
    k_node_dots<<<(NL * 32 + 255) / 256, 256>>>(NP, NL, 3, 4, 5, 300000, 380000, 460000,
                                                1, 3, 8, 100000, 230000, 610000);
    k_node_dots<<<(NG * 32 + 255) / 256, 256>>>(NP + NL, NG, 6, 7, 8, 540000, 590000, 640000,
                                                2, 5, 6, 180000, 410000, 460000);

    // bucket fill
    k_fill<<<9 * EBPR, 256>>>(ep);

    // projections H[r] = X[src(r)] @ W[r]
    for (int r = 0; r < 9; r++) {
        int M = NTY[SRC_T[r]];
        k_mma_gemm<<<(M + 127) / 128, 256, GE_SMEM>>>(XOFF3[SRC_T[r]], M, r, SOFF[r]);
    }

    // per-node softmax + gather + mean + bias + relu
    k_accum<<<(XROWS * 32 + 255) / 256, 256>>>(out, bias);
}

// round 14
// speedup vs baseline: 1.5372x; 1.5372x over previous
#include <cuda_runtime.h>
#include <cuda_bf16.h>
#include <cuda_fp16.h>
#include <cstdint>

// ---------------- problem constants ----------------
#define NP 100000
#define NL 80000
#define NG 50000
#define EDG 400000
#define DIN 512
#define DOUT 128
#define TOTROWS 690000
#define XROWS 230000
#define BCAP 64

// host-side relation tables
static const int SRC_T[9] = {0,0,0,1,1,1,2,2,2};
static const int NTY[3]   = {NP, NL, NG};
static const int XOFF3[3] = {0, NP, NP+NL};
static const int SOFF[9]  = {0,100000,200000,300000,380000,460000,540000,590000,640000};

// device-side relation tables
__constant__ int c_soff[9] = {0,100000,200000,300000,380000,460000,540000,590000,640000};
__constant__ int c_doff[9] = {0,100000,180000,230000,310000,410000,460000,510000,610000};
__constant__ int c_rel3[3][3] = {{0,4,7},{1,3,8},{2,5,6}};   // relations targeting type p/l/g

struct EdgePtrs { const int* ei[9]; };

// ---------------- device scratch ----------------
__device__ __half   g_H[(size_t)TOTROWS * DOUT];    // fp16 projected features (176 MB)
__device__ __half   g_Xf[(size_t)XROWS * DIN];      // fp16 X (235 MB)
__device__ __half   g_Wt[9 * DOUT * DIN];           // W^T fp16  [r][n][k]
__device__ float    g_ssrc[TOTROWS];
__device__ float    g_sdst[TOTROWS];
__device__ int      g_cnt[TOTROWS];                 // bucket cursors
__device__ uint2    g_ent[(size_t)TOTROWS * BCAP];  // {src, exp_bits} buckets
__device__ float    g_wv[9 * 2 * DIN];

// ---------------- helpers ----------------
__device__ __forceinline__ float dot4(float4 a, float4 b) {
    return a.x*b.x + a.y*b.y + a.z*b.z + a.w*b.w;
}
__device__ __forceinline__ uint32_t smem_u32(const void* p) {
    uint32_t a;
    asm("{ .reg .u64 t; cvta.to.shared.u64 t, %1; cvt.u32.u64 %0, t; }" : "=r"(a) : "l"(p));
    return a;
}
__device__ __forceinline__ void cp_async16(uint32_t sdst, const void* gsrc) {
    asm volatile("cp.async.cg.shared.global [%0], [%1], 16;" :: "r"(sdst), "l"(gsrc) : "memory");
}
__device__ __forceinline__ void ldm_x4(uint32_t* r, uint32_t addr) {
    asm volatile("ldmatrix.sync.aligned.m8n8.x4.shared.b16 {%0,%1,%2,%3}, [%4];"
                 : "=r"(r[0]), "=r"(r[1]), "=r"(r[2]), "=r"(r[3]) : "r"(addr));
}
__device__ __forceinline__ void mma16816h(float* d, const uint32_t* a, const uint32_t* b) {
    asm volatile("mma.sync.aligned.m16n8k16.row.col.f32.f16.f16.f32 "
                 "{%0,%1,%2,%3},{%4,%5,%6,%7},{%8,%9},{%0,%1,%2,%3};"
                 : "+f"(d[0]), "+f"(d[1]), "+f"(d[2]), "+f"(d[3])
                 : "r"(a[0]), "r"(a[1]), "r"(a[2]), "r"(a[3]), "r"(b[0]), "r"(b[1]));
}

// ---------------- K0: zero bucket cursors ----------------
__global__ void k_zero_cnt() {
    int i = blockIdx.x * blockDim.x + threadIdx.x;
    if (i < TOTROWS) g_cnt[i] = 0;
}

// ---------------- K1: convert X -> fp16 ----------------
__global__ void k_cvt_x(const float4* __restrict__ x, int n4, long long off4) {
    int i = blockIdx.x * blockDim.x + threadIdx.x;
    if (i >= n4) return;
    float4 v = x[i];
    __half2 h01 = __floats2half2_rn(v.x, v.y);
    __half2 h23 = __floats2half2_rn(v.z, v.w);
    __half2* p = (__half2*)(g_Xf + (size_t)(off4 + i) * 4);
    p[0] = h01; p[1] = h23;
}

// ---------------- K1b: W -> transposed fp16 ----------------
__global__ void k_cvt_w(const float* __restrict__ W) {
    int idx = blockIdx.x * blockDim.x + threadIdx.x;
    if (idx >= 9 * DIN * DOUT) return;
    int r = idx >> 16;
    int k = (idx >> 7) & 511;
    int n = idx & 127;
    g_Wt[(r << 16) + n * DIN + k] = __float2half_rn(W[idx]);
}

// ---------------- K2: wv[r][role] = W[r] @ a  (fp32, exact) ----------------
__global__ void k_wv(const float* __restrict__ W, const float* __restrict__ as_,
                     const float* __restrict__ ad_) {
    int idx = blockIdx.x * blockDim.x + threadIdx.x;
    if (idx >= 9 * 2 * DIN) return;
    int k = idx & (DIN - 1);
    int rr = idx >> 9;
    int role = rr & 1;
    int r = rr >> 1;
    const float* a = (role ? ad_ : as_) + r * DOUT;
    const float* w = W + (size_t)r * DIN * DOUT + (size_t)k * DOUT;
    float s = 0.f;
    #pragma unroll 8
    for (int j = 0; j < DOUT; j++) s = fmaf(w[j], a[j], s);
    g_wv[r * 1024 + role * DIN + k] = s;
}

// ---------------- K3: per-node attention logit halves (fp32 X, R12 version) ------
__device__ __forceinline__ float warp_dot512(float4 x0, float4 x1, float4 x2, float4 x3,
                                             const float* vecbase, int lane) {
    const float4* vv = (const float4*)vecbase;
    float s = dot4(x0, vv[lane]) + dot4(x1, vv[lane + 32])
            + dot4(x2, vv[lane + 64]) + dot4(x3, vv[lane + 96]);
    #pragma unroll
    for (int o = 16; o; o >>= 1) s += __shfl_xor_sync(0xffffffffu, s, o);
    return s;
}
__global__ void k_node_dots(const float* __restrict__ x, int n,
                            int r0, int r1, int r2, int so0, int so1, int so2,
                            int d0, int d1, int d2, int q0, int q1, int q2) {
    int gw   = (blockIdx.x * blockDim.x + threadIdx.x) >> 5;
    int lane = threadIdx.x & 31;
    if (gw >= n) return;
    const float4* xr = (const float4*)(x + (size_t)gw * DIN);
    float4 x0 = xr[lane], x1 = xr[lane + 32], x2 = xr[lane + 64], x3 = xr[lane + 96];
    float s;
    s = warp_dot512(x0, x1, x2, x3, g_wv + r0 * 1024,       lane); if (!lane) g_ssrc[so0 + gw] = s;
    s = warp_dot512(x0, x1, x2, x3, g_wv + r1 * 1024,       lane); if (!lane) g_ssrc[so1 + gw] = s;
    s = warp_dot512(x0, x1, x2, x3, g_wv + r2 * 1024,       lane); if (!lane) g_ssrc[so2 + gw] = s;
    s = warp_dot512(x0, x1, x2, x3, g_wv + d0 * 1024 + DIN, lane); if (!lane) g_sdst[q0 + gw] = s;
    s = warp_dot512(x0, x1, x2, x3, g_wv + d1 * 1024 + DIN, lane); if (!lane) g_sdst[q1 + gw] = s;
    s = warp_dot512(x0, x1, x2, x3, g_wv + d2 * 1024 + DIN, lane); if (!lane) g_sdst[q2 + gw] = s;
}

// ---------------- K4: fp16 single-product mma.sync GEMM ----------------
// Stage: A(10240) + B(10240) = 20480B; 2 stages = 40960B.
#define GST   20480
#define GROWB 80
#define GE_SMEM (2 * GST)

__global__ __launch_bounds__(256, 2)
void k_mma_gemm(int rowoff, int M, int rel, int hoff) {
    extern __shared__ __align__(128) char smem[];
    uint32_t sb = smem_u32(smem);
    int tid  = threadIdx.x;
    int lane = tid & 31;
    int warp = tid >> 5;
    int wm = warp & 1;
    int wn = warp >> 1;
    int tile0 = blockIdx.x * 128;

    const __half* baseA = g_Xf + (size_t)rowoff * DIN;
    const __half* baseB = g_Wt + ((size_t)rel << 16);

    float acc[4][4][4];
    #pragma unroll
    for (int i = 0; i < 4; i++)
        #pragma unroll
        for (int j = 0; j < 4; j++)
            #pragma unroll
            for (int q = 0; q < 4; q++) acc[i][j][q] = 0.f;

    auto load_chunk = [&](int c) {
        uint32_t stb = sb + (c & 1) * GST;
        int kbase = c * 32;
        #pragma unroll
        for (int t = 0; t < 2; t++) {          // A
            int id  = tid + t * 256;
            int row = id >> 2;
            int c16 = id & 3;
            int grow = tile0 + row; if (grow >= M) grow = M - 1;
            const void* g = baseA + (size_t)grow * DIN + kbase + c16 * 8;
            cp_async16(stb + row * GROWB + c16 * 16, g);
        }
        #pragma unroll
        for (int t = 0; t < 2; t++) {          // B
            int id  = tid + t * 256;
            int row = id >> 2;
            int c16 = id & 3;
            const void* g = baseB + (size_t)row * DIN + kbase + c16 * 8;
            cp_async16(stb + 10240 + row * GROWB + c16 * 16, g);
        }
        asm volatile("cp.async.commit_group;" ::: "memory");
    };

    uint32_t a_off = (uint32_t)(wm * 64 + (lane & 15)) * GROWB + (lane & 16);
    uint32_t b_off = (uint32_t)(wn * 32 + (lane & 7) + ((lane & 16) ? 8 : 0)) * GROWB
                   + ((lane & 8) << 1);

    load_chunk(0);

    for (int c = 0; c < 16; c++) {
        if (c < 15) {
            load_chunk(c + 1);
            asm volatile("cp.async.wait_group 1;" ::: "memory");
        } else {
            asm volatile("cp.async.wait_group 0;" ::: "memory");
        }
        __syncthreads();

        uint32_t stb = sb + (c & 1) * GST;
        uint32_t ah_s = stb;
        uint32_t bh_s = stb + 10240;

        #pragma unroll
        for (int ks = 0; ks < 2; ks++) {
            uint32_t kb = ks * 32;
            uint32_t AH[4][4], B[2][4];
            #pragma unroll
            for (int mf = 0; mf < 4; mf++)
                ldm_x4(AH[mf], ah_s + a_off + mf * (16 * GROWB) + kb);
            #pragma unroll
            for (int g = 0; g < 2; g++)
                ldm_x4(B[g], bh_s + b_off + g * (16 * GROWB) + kb);
            #pragma unroll
            for (int mf = 0; mf < 4; mf++)
                #pragma unroll
                for (int nf = 0; nf < 4; nf++)
                    mma16816h(acc[mf][nf], AH[mf], &B[nf >> 1][(nf & 1) * 2]);
        }
        __syncthreads();
    }

    __half* Cb = g_H + (size_t)hoff * DOUT;
    int r_base = tile0 + wm * 64 + (lane >> 2);
    int c_base = wn * 32 + (lane & 3) * 2;
    #pragma unroll
    for (int mf = 0; mf < 4; mf++) {
        #pragma unroll
        for (int nf = 0; nf < 4; nf++) {
            int r = r_base + mf * 16;
            int cc = c_base + nf * 8;
            if (r < M)
                *(__half2*)(Cb + (size_t)r * DOUT + cc)
                    = __floats2half2_rn(acc[mf][nf][0], acc[mf][nf][1]);
            if (r + 8 < M)
                *(__half2*)(Cb + (size_t)(r + 8) * DOUT + cc)
                    = __floats2half2_rn(acc[mf][nf][2], acc[mf][nf][3]);
        }
    }
}

// ---------------- K5: fill buckets (logit -> exp -> bucket append) ----------------
#define EBPR 1563
__global__ void k_fill(EdgePtrs ep) {
    int rel = blockIdx.x / EBPR;
    int e = (blockIdx.x - rel * EBPR) * 256 + threadIdx.x;
    if (e >= EDG) return;
    const int* ei = ep.ei[rel];
    int s = ei[e], d = ei[EDG + e];
    float a = g_ssrc[c_soff[rel] + s] + g_sdst[c_doff[rel] + d];
    a = (a > 0.f) ? a : 0.2f * a;
    float v = __expf(a);               // logits bounded: max-sub unnecessary
    int slot = c_doff[rel] + d;
    int pos = atomicAdd(&g_cnt[slot], 1);
    if (pos < BCAP)
        g_ent[(size_t)slot * BCAP + pos] = make_uint2((unsigned)s, __float_as_uint(v));
}

// ---------------- K6: per-node accumulation (softmax + gather + mean + bias + relu) ----
__global__ void k_accum(float* __restrict__ out, const float* __restrict__ bias) {
    int gw   = (blockIdx.x * blockDim.x + threadIdx.x) >> 5;
    int lane = threadIdx.x & 31;
    if (gw >= XROWS) return;
    int ty, d;
    if (gw < NP)           { ty = 0; d = gw; }
    else if (gw < NP + NL) { ty = 1; d = gw - NP; }
    else                   { ty = 2; d = gw - NP - NL; }

    float acc0 = 0.f, acc1 = 0.f, acc2 = 0.f, acc3 = 0.f;
    float4 bsum = make_float4(0.f, 0.f, 0.f, 0.f);

    #pragma unroll
    for (int q = 0; q < 3; q++) {
        int r = c_rel3[ty][q];
        float4 bv = *(const float4*)(bias + r * DOUT + lane * 4);
        bsum.x += bv.x; bsum.y += bv.y; bsum.z += bv.z; bsum.w += bv.w;

        int slot = c_doff[r] + d;
        int cnt = g_cnt[slot]; if (cnt > BCAP) cnt = BCAP;
        if (cnt == 0) continue;
        const uint2* lst = g_ent + (size_t)slot * BCAP;
        float den = 0.f;
        for (int j = 0; j < cnt; j++) den += __uint_as_float(lst[j].y);
        float inv = 1.f / den;
        const __half* Hb = g_H + (size_t)c_soff[r] * DOUT;
        for (int j = 0; j < cnt; j++) {
            uint2 en = lst[j];
            float wt = __uint_as_float(en.y) * inv;
            uint2 u = *(const uint2*)(Hb + (size_t)en.x * DOUT + lane * 4);
            float2 f0 = __half22float2(*(__half2*)&u.x);
            float2 f1 = __half22float2(*(__half2*)&u.y);
            acc0 = fmaf(f0.x, wt, acc0);
            acc1 = fmaf(f0.y, wt, acc1);
            acc2 = fmaf(f1.x, wt, acc2);
            acc3 = fmaf(f1.y, wt, acc3);
        }
    }

    float4 o;
    o.x = (acc0 + bsum.x) * (1.0f / 3.0f);
    o.y = (acc1 + bsum.y) * (1.0f / 3.0f);
    o.z = (acc2 + bsum.z) * (1.0f / 3.0f);
    o.w = (acc3 + bsum.w) * (1.0f / 3.0f);
    o.x = o.x > 0.f ? o.x : 0.f;
    o.y = o.y > 0.f ? o.y : 0.f;
    o.z = o.z > 0.f ? o.z : 0.f;
    o.w = o.w > 0.f ? o.w : 0.f;
    *(float4*)(out + (size_t)gw * DOUT + lane * 4) = o;
}

// ---------------- launch ----------------
extern "C" void kernel_launch(void* const* d_in, const int* in_sizes, int n_in,
                              void* d_out, int out_size) {
    const float* X[3] = {(const float*)d_in[0], (const float*)d_in[1], (const float*)d_in[2]};
    EdgePtrs ep;
    for (int r = 0; r < 9; r++) ep.ei[r] = (const int*)d_in[3 + r];
    const float* W    = (const float*)d_in[12];
    const float* as_  = (const float*)d_in[13];
    const float* ad_  = (const float*)d_in[14];
    const float* bias = (const float*)d_in[15];
    float* out = (float*)d_out;

    cudaFuncSetAttribute(k_mma_gemm, cudaFuncAttributeMaxDynamicSharedMemorySize, GE_SMEM);

    // init bucket cursors
    k_zero_cnt<<<(TOTROWS + 255) / 256, 256>>>();

    // conversions
    k_cvt_x<<<(NP * 128 + 255) / 256, 256>>>((const float4*)X[0], NP * 128, 0LL);
    k_cvt_x<<<(NL * 128 + 255) / 256, 256>>>((const float4*)X[1], NL * 128, (long long)NP * 128);
    k_cvt_x<<<(NG * 128 + 255) / 256, 256>>>((const float4*)X[2], NG * 128, (long long)(NP + NL) * 128);
    k_cvt_w<<<(9 * DIN * DOUT + 255) / 256, 256>>>(W);

    // attention-vector precompute + per-node logit halves (fp32 X)
    k_wv<<<(9 * 2 * DIN + 255) / 256, 256>>>(W, as_, ad_);
    k_node_dots<<<(NP * 32 + 255) / 256, 256>>>(X[0], NP, 0, 1, 2, 0, 100000, 200000,
                                                0, 4, 7, 0, 310000, 510000);
    k_node_dots<<<(NL * 32 + 255) / 256, 256>>>(X[1], NL, 3, 4, 5, 300000, 380000, 460000,
                                                1, 3, 8, 100000, 230000, 610000);
    k_node_dots<<<(NG * 32 + 255) / 256, 256>>>(X[2], NG, 6, 7, 8, 540000, 590000, 640000,
                                                2, 5, 6, 180000, 410000, 460000);

    // bucket fill
    k_fill<<<9 * EBPR, 256>>>(ep);

    // projections H[r] = X[src(r)] @ W[r]
    for (int r = 0; r < 9; r++) {
        int M = NTY[SRC_T[r]];
        k_mma_gemm<<<(M + 127) / 128, 256, GE_SMEM>>>(XOFF3[SRC_T[r]], M, r, SOFF[r]);
    }

    // per-node softmax + gather + mean + bias + relu
    k_accum<<<(XROWS * 32 + 255) / 256, 256>>>(out, bias);
}

// round 15
// speedup vs baseline: 1.5950x; 1.0376x over previous
#include <cuda_runtime.h>
#include <cuda_bf16.h>
#include <cuda_fp16.h>
#include <cstdint>

// ---------------- problem constants ----------------
#define NP 100000
#define NL 80000
#define NG 50000
#define EDG 400000
#define DIN 512
#define DOUT 128
#define TOTROWS 690000
#define XROWS 230000
#define BCAP 64

// host-side relation tables
static const int SRC_T[9] = {0,0,0,1,1,1,2,2,2};
static const int NTY[3]   = {NP, NL, NG};
static const int XOFF3[3] = {0, NP, NP+NL};
static const int SOFF[9]  = {0,100000,200000,300000,380000,460000,540000,590000,640000};
static const int DOFF9[9] = {0,100000,180000,230000,310000,410000,460000,510000,610000};
static const int SAME9[9] = {1,0,0,1,0,0,1,0,0};

// device-side relation tables
__constant__ int c_soff[9] = {0,100000,200000,300000,380000,460000,540000,590000,640000};
__constant__ int c_doff[9] = {0,100000,180000,230000,310000,410000,460000,510000,610000};
__constant__ int c_rel3[3][3] = {{0,4,7},{1,3,8},{2,5,6}};   // relations targeting type p/l/g

struct EdgePtrs { const int* ei[9]; };

// ---------------- device scratch ----------------
__device__ __half   g_H[(size_t)TOTROWS * DOUT];    // fp16 projected features (176 MB)
__device__ __half   g_Xf[(size_t)XROWS * DIN];      // fp16 X (235 MB)
__device__ __half   g_Wt[9 * DOUT * DIN];           // W^T fp16  [r][n][k]
__device__ float    g_ssrc[TOTROWS];
__device__ float    g_sdst[TOTROWS];
__device__ int      g_cnt[TOTROWS];                 // bucket cursors
__device__ uint2    g_ent[(size_t)TOTROWS * BCAP];  // {src, exp_bits} buckets
__device__ float    g_wv[9 * 2 * DIN];

// ---------------- helpers ----------------
__device__ __forceinline__ float dot4(float4 a, float4 b) {
    return a.x*b.x + a.y*b.y + a.z*b.z + a.w*b.w;
}
__device__ __forceinline__ uint32_t smem_u32(const void* p) {
    uint32_t a;
    asm("{ .reg .u64 t; cvta.to.shared.u64 t, %1; cvt.u32.u64 %0, t; }" : "=r"(a) : "l"(p));
    return a;
}
__device__ __forceinline__ void cp_async16(uint32_t sdst, const void* gsrc) {
    asm volatile("cp.async.cg.shared.global [%0], [%1], 16;" :: "r"(sdst), "l"(gsrc) : "memory");
}
__device__ __forceinline__ void ldm_x4(uint32_t* r, uint32_t addr) {
    asm volatile("ldmatrix.sync.aligned.m8n8.x4.shared.b16 {%0,%1,%2,%3}, [%4];"
                 : "=r"(r[0]), "=r"(r[1]), "=r"(r[2]), "=r"(r[3]) : "r"(addr));
}
__device__ __forceinline__ void mma16816h(float* d, const uint32_t* a, const uint32_t* b) {
    asm volatile("mma.sync.aligned.m16n8k16.row.col.f32.f16.f16.f32 "
                 "{%0,%1,%2,%3},{%4,%5,%6,%7},{%8,%9},{%0,%1,%2,%3};"
                 : "+f"(d[0]), "+f"(d[1]), "+f"(d[2]), "+f"(d[3])
                 : "r"(a[0]), "r"(a[1]), "r"(a[2]), "r"(a[3]), "r"(b[0]), "r"(b[1]));
}

// ---------------- K0: zero cursors + logit accumulators ----------------
__global__ void k_zero_cnt() {
    int i = blockIdx.x * blockDim.x + threadIdx.x;
    if (i < TOTROWS) { g_cnt[i] = 0; g_ssrc[i] = 0.f; g_sdst[i] = 0.f; }
}

// ---------------- K1: convert X -> fp16 ----------------
__global__ void k_cvt_x(const float4* __restrict__ x, int n4, long long off4) {
    int i = blockIdx.x * blockDim.x + threadIdx.x;
    if (i >= n4) return;
    float4 v = x[i];
    __half2 h01 = __floats2half2_rn(v.x, v.y);
    __half2 h23 = __floats2half2_rn(v.z, v.w);
    __half2* p = (__half2*)(g_Xf + (size_t)(off4 + i) * 4);
    p[0] = h01; p[1] = h23;
}

// ---------------- K1b: W -> transposed fp16 ----------------
__global__ void k_cvt_w(const float* __restrict__ W) {
    int idx = blockIdx.x * blockDim.x + threadIdx.x;
    if (idx >= 9 * DIN * DOUT) return;
    int r = idx >> 16;
    int k = (idx >> 7) & 511;
    int n = idx & 127;
    g_Wt[(r << 16) + n * DIN + k] = __float2half_rn(W[idx]);
}

// ---------------- K2: wv[r][dst] = W[r] @ a_d  (fp32, exact) ----------------
__global__ void k_wv(const float* __restrict__ W, const float* __restrict__ ad_) {
    int idx = blockIdx.x * blockDim.x + threadIdx.x;
    if (idx >= 9 * DIN) return;
    int k = idx & (DIN - 1);
    int r = idx >> 9;
    const float* a = ad_ + r * DOUT;
    const float* w = W + (size_t)r * DIN * DOUT + (size_t)k * DOUT;
    float s = 0.f;
    #pragma unroll 8
    for (int j = 0; j < DOUT; j++) s = fmaf(w[j], a[j], s);
    g_wv[r * 1024 + DIN + k] = s;
}

// ---------------- K3: cross-type dst logits only (2 warp dots / node) ----------
__device__ __forceinline__ float warp_dot512(float4 x0, float4 x1, float4 x2, float4 x3,
                                             const float* vecbase, int lane) {
    const float4* vv = (const float4*)vecbase;
    float s = dot4(x0, vv[lane]) + dot4(x1, vv[lane + 32])
            + dot4(x2, vv[lane + 64]) + dot4(x3, vv[lane + 96]);
    #pragma unroll
    for (int o = 16; o; o >>= 1) s += __shfl_xor_sync(0xffffffffu, s, o);
    return s;
}
__global__ void k_node_dots2(const float* __restrict__ x, int n,
                             int ra, int qa, int rb, int qb) {
    int gw   = (blockIdx.x * blockDim.x + threadIdx.x) >> 5;
    int lane = threadIdx.x & 31;
    if (gw >= n) return;
    const float4* xr = (const float4*)(x + (size_t)gw * DIN);
    float4 x0 = xr[lane], x1 = xr[lane + 32], x2 = xr[lane + 64], x3 = xr[lane + 96];
    float s;
    s = warp_dot512(x0, x1, x2, x3, g_wv + ra * 1024 + DIN, lane); if (!lane) g_sdst[qa + gw] = s;
    s = warp_dot512(x0, x1, x2, x3, g_wv + rb * 1024 + DIN, lane); if (!lane) g_sdst[qb + gw] = s;
}

// ---------------- K4: fp16 single-product GEMM + fused <h,a> epilogue ----------
#define GST   20480
#define GROWB 80
#define GE_SMEM (2 * GST)

__global__ __launch_bounds__(256, 2)
void k_mma_gemm(int rowoff, int M, int rel, int hoff,
                const float* __restrict__ att_src, const float* __restrict__ att_dst,
                int doff, int same) {
    extern __shared__ __align__(128) char smem[];
    uint32_t sb = smem_u32(smem);
    int tid  = threadIdx.x;
    int lane = tid & 31;
    int warp = tid >> 5;
    int wm = warp & 1;
    int wn = warp >> 1;
    int tile0 = blockIdx.x * 128;

    const __half* baseA = g_Xf + (size_t)rowoff * DIN;
    const __half* baseB = g_Wt + ((size_t)rel << 16);

    float acc[4][4][4];
    #pragma unroll
    for (int i = 0; i < 4; i++)
        #pragma unroll
        for (int j = 0; j < 4; j++)
            #pragma unroll
            for (int q = 0; q < 4; q++) acc[i][j][q] = 0.f;

    auto load_chunk = [&](int c) {
        uint32_t stb = sb + (c & 1) * GST;
        int kbase = c * 32;
        #pragma unroll
        for (int t = 0; t < 2; t++) {          // A
            int id  = tid + t * 256;
            int row = id >> 2;
            int c16 = id & 3;
            int grow = tile0 + row; if (grow >= M) grow = M - 1;
            const void* g = baseA + (size_t)grow * DIN + kbase + c16 * 8;
            cp_async16(stb + row * GROWB + c16 * 16, g);
        }
        #pragma unroll
        for (int t = 0; t < 2; t++) {          // B
            int id  = tid + t * 256;
            int row = id >> 2;
            int c16 = id & 3;
            const void* g = baseB + (size_t)row * DIN + kbase + c16 * 8;
            cp_async16(stb + 10240 + row * GROWB + c16 * 16, g);
        }
        asm volatile("cp.async.commit_group;" ::: "memory");
    };

    uint32_t a_off = (uint32_t)(wm * 64 + (lane & 15)) * GROWB + (lane & 16);
    uint32_t b_off = (uint32_t)(wn * 32 + (lane & 7) + ((lane & 16) ? 8 : 0)) * GROWB
                   + ((lane & 8) << 1);

    load_chunk(0);

    for (int c = 0; c < 16; c++) {
        if (c < 15) {
            load_chunk(c + 1);
            asm volatile("cp.async.wait_group 1;" ::: "memory");
        } else {
            asm volatile("cp.async.wait_group 0;" ::: "memory");
        }
        __syncthreads();

        uint32_t stb = sb + (c & 1) * GST;
        uint32_t ah_s = stb;
        uint32_t bh_s = stb + 10240;

        #pragma unroll
        for (int ks = 0; ks < 2; ks++) {
            uint32_t kb = ks * 32;
            uint32_t AH[4][4], B[2][4];
            #pragma unroll
            for (int mf = 0; mf < 4; mf++)
                ldm_x4(AH[mf], ah_s + a_off + mf * (16 * GROWB) + kb);
            #pragma unroll
            for (int g = 0; g < 2; g++)
                ldm_x4(B[g], bh_s + b_off + g * (16 * GROWB) + kb);
            #pragma unroll
            for (int mf = 0; mf < 4; mf++)
                #pragma unroll
                for (int nf = 0; nf < 4; nf++)
                    mma16816h(acc[mf][nf], AH[mf], &B[nf >> 1][(nf & 1) * 2]);
        }
        __syncthreads();
    }

    // ---- epilogue: store H (fp16) + fused <h,a_src> (and <h,a_dst> if same-type) ----
    __half* Cb = g_H + (size_t)hoff * DOUT;
    int r_base = tile0 + wm * 64 + (lane >> 2);
    int c_base = wn * 32 + (lane & 3) * 2;

    float2 asv[4], adv[4];
    #pragma unroll
    for (int nf = 0; nf < 4; nf++) {
        asv[nf] = *(const float2*)(att_src + rel * DOUT + c_base + nf * 8);
        adv[nf] = same ? *(const float2*)(att_dst + rel * DOUT + c_base + nf * 8)
                       : make_float2(0.f, 0.f);
    }

    #pragma unroll
    for (int mf = 0; mf < 4; mf++) {
        #pragma unroll
        for (int h = 0; h < 2; h++) {
            int r = r_base + mf * 16 + 8 * h;
            bool ok = (r < M);
            #pragma unroll
            for (int nf = 0; nf < 4; nf++) {
                if (ok)
                    *(__half2*)(Cb + (size_t)r * DOUT + c_base + nf * 8)
                        = __floats2half2_rn(acc[mf][nf][2*h], acc[mf][nf][2*h + 1]);
            }
            float ps = 0.f, pd = 0.f;
            #pragma unroll
            for (int nf = 0; nf < 4; nf++) {
                ps += acc[mf][nf][2*h] * asv[nf].x + acc[mf][nf][2*h + 1] * asv[nf].y;
                pd += acc[mf][nf][2*h] * adv[nf].x + acc[mf][nf][2*h + 1] * adv[nf].y;
            }
            ps += __shfl_xor_sync(0xffffffffu, ps, 1);
            ps += __shfl_xor_sync(0xffffffffu, ps, 2);
            pd += __shfl_xor_sync(0xffffffffu, pd, 1);
            pd += __shfl_xor_sync(0xffffffffu, pd, 2);
            if ((lane & 3) == 0 && ok) {
                atomicAdd(&g_ssrc[hoff + r], ps);
                if (same) atomicAdd(&g_sdst[doff + r], pd);
            }
        }
    }
}

// ---------------- K5: fill buckets (logit -> exp -> bucket append) ----------------
#define EBPR 1563
__global__ void k_fill(EdgePtrs ep) {
    int rel = blockIdx.x / EBPR;
    int e = (blockIdx.x - rel * EBPR) * 256 + threadIdx.x;
    if (e >= EDG) return;
    const int* ei = ep.ei[rel];
    int s = ei[e], d = ei[EDG + e];
    float a = g_ssrc[c_soff[rel] + s] + g_sdst[c_doff[rel] + d];
    a = (a > 0.f) ? a : 0.2f * a;
    float v = __expf(a);               // logits bounded: max-sub unnecessary
    int slot = c_doff[rel] + d;
    int pos = atomicAdd(&g_cnt[slot], 1);
    if (pos < BCAP)
        g_ent[(size_t)slot * BCAP + pos] = make_uint2((unsigned)s, __float_as_uint(v));
}

// ---------------- K6: per-node accumulation (softmax + gather + mean + bias + relu) ----
__global__ void k_accum(float* __restrict__ out, const float* __restrict__ bias) {
    int gw   = (blockIdx.x * blockDim.x + threadIdx.x) >> 5;
    int lane = threadIdx.x & 31;
    if (gw >= XROWS) return;
    int ty, d;
    if (gw < NP)           { ty = 0; d = gw; }
    else if (gw < NP + NL) { ty = 1; d = gw - NP; }
    else                   { ty = 2; d = gw - NP - NL; }

    float acc0 = 0.f, acc1 = 0.f, acc2 = 0.f, acc3 = 0.f;
    float4 bsum = make_float4(0.f, 0.f, 0.f, 0.f);

    #pragma unroll
    for (int q = 0; q < 3; q++) {
        int r = c_rel3[ty][q];
        float4 bv = *(const float4*)(bias + r * DOUT + lane * 4);
        bsum.x += bv.x; bsum.y += bv.y; bsum.z += bv.z; bsum.w += bv.w;

        int slot = c_doff[r] + d;
        int cnt = g_cnt[slot]; if (cnt > BCAP) cnt = BCAP;
        if (cnt == 0) continue;
        const uint2* lst = g_ent + (size_t)slot * BCAP;
        float den = 0.f;
        for (int j = 0; j < cnt; j++) den += __uint_as_float(lst[j].y);
        float inv = 1.f / den;
        const __half* Hb = g_H + (size_t)c_soff[r] * DOUT;
        for (int j = 0; j < cnt; j++) {
            uint2 en = lst[j];
            float wt = __uint_as_float(en.y) * inv;
            uint2 u = *(const uint2*)(Hb + (size_t)en.x * DOUT + lane * 4);
            float2 f0 = __half22float2(*(__half2*)&u.x);
            float2 f1 = __half22float2(*(__half2*)&u.y);
            acc0 = fmaf(f0.x, wt, acc0);
            acc1 = fmaf(f0.y, wt, acc1);
            acc2 = fmaf(f1.x, wt, acc2);
            acc3 = fmaf(f1.y, wt, acc3);
        }
    }

    float4 o;
    o.x = (acc0 + bsum.x) * (1.0f / 3.0f);
    o.y = (acc1 + bsum.y) * (1.0f / 3.0f);
    o.z = (acc2 + bsum.z) * (1.0f / 3.0f);
    o.w = (acc3 + bsum.w) * (1.0f / 3.0f);
    o.x = o.x > 0.f ? o.x : 0.f;
    o.y = o.y > 0.f ? o.y : 0.f;
    o.z = o.z > 0.f ? o.z : 0.f;
    o.w = o.w > 0.f ? o.w : 0.f;
    *(float4*)(out + (size_t)gw * DOUT + lane * 4) = o;
}

// ---------------- launch ----------------
extern "C" void kernel_launch(void* const* d_in, const int* in_sizes, int n_in,
                              void* d_out, int out_size) {
    const float* X[3] = {(const float*)d_in[0], (const float*)d_in[1], (const float*)d_in[2]};
    EdgePtrs ep;
    for (int r = 0; r < 9; r++) ep.ei[r] = (const int*)d_in[3 + r];
    const float* W    = (const float*)d_in[12];
    const float* as_  = (const float*)d_in[13];
    const float* ad_  = (const float*)d_in[14];
    const float* bias = (const float*)d_in[15];
    float* out = (float*)d_out;

    cudaFuncSetAttribute(k_mma_gemm, cudaFuncAttributeMaxDynamicSharedMemorySize, GE_SMEM);

    // init cursors + logit accumulators
    k_zero_cnt<<<(TOTROWS + 255) / 256, 256>>>();

    // conversions
    k_cvt_x<<<(NP * 128 + 255) / 256, 256>>>((const float4*)X[0], NP * 128, 0LL);
    k_cvt_x<<<(NL * 128 + 255) / 256, 256>>>((const float4*)X[1], NL * 128, (long long)NP * 128);
    k_cvt_x<<<(NG * 128 + 255) / 256, 256>>>((const float4*)X[2], NG * 128, (long long)(NP + NL) * 128);
    k_cvt_w<<<(9 * DIN * DOUT + 255) / 256, 256>>>(W);

    // dst attention matvec precompute + cross-type dst logits (fp32 X)
    k_wv<<<(9 * DIN + 255) / 256, 256>>>(W, ad_);
    k_node_dots2<<<(NP * 32 + 255) / 256, 256>>>(X[0], NP, 4, 310000, 7, 510000);
    k_node_dots2<<<(NL * 32 + 255) / 256, 256>>>(X[1], NL, 1, 100000, 8, 610000);
    k_node_dots2<<<(NG * 32 + 255) / 256, 256>>>(X[2], NG, 2, 180000, 5, 410000);

    // projections H[r] = X[src(r)] @ W[r]  (+ fused ssrc / same-type sdst)
    for (int r = 0; r < 9; r++) {
        int M = NTY[SRC_T[r]];
        k_mma_gemm<<<(M + 127) / 128, 256, GE_SMEM>>>(XOFF3[SRC_T[r]], M, r, SOFF[r],
                                                      as_, ad_, DOFF9[r], SAME9[r]);
    }

    // bucket fill (consumes ssrc/sdst)
    k_fill<<<9 * EBPR, 256>>>(ep);

    // per-node softmax + gather + mean + bias + relu
    k_accum<<<(XROWS * 32 + 255) / 256, 256>>>(out, bias);
}

// round 17
// speedup vs baseline: 1.6001x; 1.0032x over previous
#include <cuda_runtime.h>
#include <cuda_bf16.h>
#include <cuda_fp16.h>
#include <cstdint>

// ---------------- problem constants ----------------
#define NP 100000
#define NL 80000
#define NG 50000
#define EDG 400000
#define DIN 512
#define DOUT 128
#define TOTROWS 690000
#define XROWS 230000
#define BCAP 64

// host-side relation tables
static const int SRC_T[9] = {0,0,0,1,1,1,2,2,2};
static const int NTY[3]   = {NP, NL, NG};
static const int XOFF3[3] = {0, NP, NP+NL};
static const int SOFF[9]  = {0,100000,200000,300000,380000,460000,540000,590000,640000};
static const int DOFF9[9] = {0,100000,180000,230000,310000,410000,460000,510000,610000};
static const int SAME9[9] = {1,0,0,1,0,0,1,0,0};

// device-side relation tables
__constant__ int c_soff[9] = {0,100000,200000,300000,380000,460000,540000,590000,640000};
__constant__ int c_doff[9] = {0,100000,180000,230000,310000,410000,460000,510000,610000};
__constant__ int c_rel3[3][3] = {{0,4,7},{1,3,8},{2,5,6}};   // relations targeting type p/l/g

struct EdgePtrs { const int* ei[9]; };

// ---------------- device scratch ----------------
__device__ __half   g_H[(size_t)TOTROWS * DOUT];    // fp16 projected features (176 MB)
__device__ __half   g_Xf[(size_t)XROWS * DIN];      // fp16 X (235 MB)
__device__ __half   g_Wt[9 * DOUT * DIN];           // W^T fp16  [r][n][k]
__device__ float    g_ssrc[TOTROWS];
__device__ float    g_sdst[TOTROWS];
__device__ int      g_cnt[TOTROWS];                 // bucket cursors
__device__ uint2    g_ent[(size_t)TOTROWS * BCAP];  // {src, exp_bits} buckets
__device__ float    g_wv[9 * 2 * DIN];

// ---------------- helpers ----------------
__device__ __forceinline__ float dot4(float4 a, float4 b) {
    return a.x*b.x + a.y*b.y + a.z*b.z + a.w*b.w;
}
__device__ __forceinline__ uint32_t smem_u32(const void* p) {
    uint32_t a;
    asm("{ .reg .u64 t; cvta.to.shared.u64 t, %1; cvt.u32.u64 %0, t; }" : "=r"(a) : "l"(p));
    return a;
}
__device__ __forceinline__ void cp_async16(uint32_t sdst, const void* gsrc) {
    asm volatile("cp.async.cg.shared.global [%0], [%1], 16;" :: "r"(sdst), "l"(gsrc) : "memory");
}
__device__ __forceinline__ void ldm_x4(uint32_t* r, uint32_t addr) {
    asm volatile("ldmatrix.sync.aligned.m8n8.x4.shared.b16 {%0,%1,%2,%3}, [%4];"
                 : "=r"(r[0]), "=r"(r[1]), "=r"(r[2]), "=r"(r[3]) : "r"(addr));
}
__device__ __forceinline__ void mma16816h(float* d, const uint32_t* a, const uint32_t* b) {
    asm volatile("mma.sync.aligned.m16n8k16.row.col.f32.f16.f16.f32 "
                 "{%0,%1,%2,%3},{%4,%5,%6,%7},{%8,%9},{%0,%1,%2,%3};"
                 : "+f"(d[0]), "+f"(d[1]), "+f"(d[2]), "+f"(d[3])
                 : "r"(a[0]), "r"(a[1]), "r"(a[2]), "r"(a[3]), "r"(b[0]), "r"(b[1]));
}

// ---------------- K0: zero cursors + logit accumulators ----------------
__global__ void k_zero_cnt() {
    int i = blockIdx.x * blockDim.x + threadIdx.x;
    if (i < TOTROWS) { g_cnt[i] = 0; g_ssrc[i] = 0.f; g_sdst[i] = 0.f; }
}

// ---------------- K1: convert X -> fp16 ----------------
__global__ void k_cvt_x(const float4* __restrict__ x, int n4, long long off4) {
    int i = blockIdx.x * blockDim.x + threadIdx.x;
    if (i >= n4) return;
    float4 v = x[i];
    __half2 h01 = __floats2half2_rn(v.x, v.y);
    __half2 h23 = __floats2half2_rn(v.z, v.w);
    __half2* p = (__half2*)(g_Xf + (size_t)(off4 + i) * 4);
    p[0] = h01; p[1] = h23;
}

// ---------------- K1b: W -> transposed fp16 ----------------
__global__ void k_cvt_w(const float* __restrict__ W) {
    int idx = blockIdx.x * blockDim.x + threadIdx.x;
    if (idx >= 9 * DIN * DOUT) return;
    int r = idx >> 16;
    int k = (idx >> 7) & 511;
    int n = idx & 127;
    g_Wt[(r << 16) + n * DIN + k] = __float2half_rn(W[idx]);
}

// ---------------- K2: wv[r][dst] = W[r] @ a_d  (fp32, exact) ----------------
__global__ void k_wv(const float* __restrict__ W, const float* __restrict__ ad_) {
    int idx = blockIdx.x * blockDim.x + threadIdx.x;
    if (idx >= 9 * DIN) return;
    int k = idx & (DIN - 1);
    int r = idx >> 9;
    const float* a = ad_ + r * DOUT;
    const float* w = W + (size_t)r * DIN * DOUT + (size_t)k * DOUT;
    float s = 0.f;
    #pragma unroll 8
    for (int j = 0; j < DOUT; j++) s = fmaf(w[j], a[j], s);
    g_wv[r * 1024 + DIN + k] = s;
}

// ---------------- K3: cross-type dst logits only (2 warp dots / node) ----------
__device__ __forceinline__ float warp_dot512(float4 x0, float4 x1, float4 x2, float4 x3,
                                             const float* vecbase, int lane) {
    const float4* vv = (const float4*)vecbase;
    float s = dot4(x0, vv[lane]) + dot4(x1, vv[lane + 32])
            + dot4(x2, vv[lane + 64]) + dot4(x3, vv[lane + 96]);
    #pragma unroll
    for (int o = 16; o; o >>= 1) s += __shfl_xor_sync(0xffffffffu, s, o);
    return s;
}
__global__ void k_node_dots2(const float* __restrict__ x, int n,
                             int ra, int qa, int rb, int qb) {
    int gw   = (blockIdx.x * blockDim.x + threadIdx.x) >> 5;
    int lane = threadIdx.x & 31;
    if (gw >= n) return;
    const float4* xr = (const float4*)(x + (size_t)gw * DIN);
    float4 x0 = xr[lane], x1 = xr[lane + 32], x2 = xr[lane + 64], x3 = xr[lane + 96];
    float s;
    s = warp_dot512(x0, x1, x2, x3, g_wv + ra * 1024 + DIN, lane); if (!lane) g_sdst[qa + gw] = s;
    s = warp_dot512(x0, x1, x2, x3, g_wv + rb * 1024 + DIN, lane); if (!lane) g_sdst[qb + gw] = s;
}

// ---------------- K4: fp16 single-product GEMM + fused <h,a> epilogue ----------
#define GST   20480
#define GROWB 80
#define GE_SMEM (2 * GST)

__global__ __launch_bounds__(256, 2)
void k_mma_gemm(int rowoff, int M, int rel, int hoff,
                const float* __restrict__ att_src, const float* __restrict__ att_dst,
                int doff, int same) {
    extern __shared__ __align__(128) char smem[];
    uint32_t sb = smem_u32(smem);
    int tid  = threadIdx.x;
    int lane = tid & 31;
    int warp = tid >> 5;
    int wm = warp & 1;
    int wn = warp >> 1;
    int tile0 = blockIdx.x * 128;

    const __half* baseA = g_Xf + (size_t)rowoff * DIN;
    const __half* baseB = g_Wt + ((size_t)rel << 16);

    float acc[4][4][4];
    #pragma unroll
    for (int i = 0; i < 4; i++)
        #pragma unroll
        for (int j = 0; j < 4; j++)
            #pragma unroll
            for (int q = 0; q < 4; q++) acc[i][j][q] = 0.f;

    auto load_chunk = [&](int c) {
        uint32_t stb = sb + (c & 1) * GST;
        int kbase = c * 32;
        #pragma unroll
        for (int t = 0; t < 2; t++) {          // A
            int id  = tid + t * 256;
            int row = id >> 2;
            int c16 = id & 3;
            int grow = tile0 + row; if (grow >= M) grow = M - 1;
            const void* g = baseA + (size_t)grow * DIN + kbase + c16 * 8;
            cp_async16(stb + row * GROWB + c16 * 16, g);
        }
        #pragma unroll
        for (int t = 0; t < 2; t++) {          // B
            int id  = tid + t * 256;
            int row = id >> 2;
            int c16 = id & 3;
            const void* g = baseB + (size_t)row * DIN + kbase + c16 * 8;
            cp_async16(stb + 10240 + row * GROWB + c16 * 16, g);
        }
        asm volatile("cp.async.commit_group;" ::: "memory");
    };

    uint32_t a_off = (uint32_t)(wm * 64 + (lane & 15)) * GROWB + (lane & 16);
    uint32_t b_off = (uint32_t)(wn * 32 + (lane & 7) + ((lane & 16) ? 8 : 0)) * GROWB
                   + ((lane & 8) << 1);

    load_chunk(0);

    for (int c = 0; c < 16; c++) {
        if (c < 15) {
            load_chunk(c + 1);
            asm volatile("cp.async.wait_group 1;" ::: "memory");
        } else {
            asm volatile("cp.async.wait_group 0;" ::: "memory");
        }
        __syncthreads();

        uint32_t stb = sb + (c & 1) * GST;
        uint32_t ah_s = stb;
        uint32_t bh_s = stb + 10240;

        #pragma unroll
        for (int ks = 0; ks < 2; ks++) {
            uint32_t kb = ks * 32;
            uint32_t AH[4][4], B[2][4];
            #pragma unroll
            for (int mf = 0; mf < 4; mf++)
                ldm_x4(AH[mf], ah_s + a_off + mf * (16 * GROWB) + kb);
            #pragma unroll
            for (int g = 0; g < 2; g++)
                ldm_x4(B[g], bh_s + b_off + g * (16 * GROWB) + kb);
            #pragma unroll
            for (int mf = 0; mf < 4; mf++)
                #pragma unroll
                for (int nf = 0; nf < 4; nf++)
                    mma16816h(acc[mf][nf], AH[mf], &B[nf >> 1][(nf & 1) * 2]);
        }
        __syncthreads();
    }

    // ---- epilogue: store H (fp16) + fused <h,a_src> (and <h,a_dst> if same-type) ----
    __half* Cb = g_H + (size_t)hoff * DOUT;
    int r_base = tile0 + wm * 64 + (lane >> 2);
    int c_base = wn * 32 + (lane & 3) * 2;

    float2 asv[4], adv[4];
    #pragma unroll
    for (int nf = 0; nf < 4; nf++) {
        asv[nf] = *(const float2*)(att_src + rel * DOUT + c_base + nf * 8);
        adv[nf] = same ? *(const float2*)(att_dst + rel * DOUT + c_base + nf * 8)
                       : make_float2(0.f, 0.f);
    }

    #pragma unroll
    for (int mf = 0; mf < 4; mf++) {
        #pragma unroll
        for (int h = 0; h < 2; h++) {
            int r = r_base + mf * 16 + 8 * h;
            bool ok = (r < M);
            #pragma unroll
            for (int nf = 0; nf < 4; nf++) {
                if (ok)
                    *(__half2*)(Cb + (size_t)r * DOUT + c_base + nf * 8)
                        = __floats2half2_rn(acc[mf][nf][2*h], acc[mf][nf][2*h + 1]);
            }
            float ps = 0.f, pd = 0.f;
            #pragma unroll
            for (int nf = 0; nf < 4; nf++) {
                ps += acc[mf][nf][2*h] * asv[nf].x + acc[mf][nf][2*h + 1] * asv[nf].y;
                pd += acc[mf][nf][2*h] * adv[nf].x + acc[mf][nf][2*h + 1] * adv[nf].y;
            }
            ps += __shfl_xor_sync(0xffffffffu, ps, 1);
            ps += __shfl_xor_sync(0xffffffffu, ps, 2);
            pd += __shfl_xor_sync(0xffffffffu, pd, 1);
            pd += __shfl_xor_sync(0xffffffffu, pd, 2);
            if ((lane & 3) == 0 && ok) {
                atomicAdd(&g_ssrc[hoff + r], ps);
                if (same) atomicAdd(&g_sdst[doff + r], pd);
            }
        }
    }
}

// ---------------- K5: fill buckets (logit -> exp -> bucket append) ----------------
#define EBPR 1563
__global__ void k_fill(EdgePtrs ep) {
    int rel = blockIdx.x / EBPR;
    int e = (blockIdx.x - rel * EBPR) * 256 + threadIdx.x;
    if (e >= EDG) return;
    const int* ei = ep.ei[rel];
    int s = ei[e], d = ei[EDG + e];
    float a = g_ssrc[c_soff[rel] + s] + g_sdst[c_doff[rel] + d];
    a = (a > 0.f) ? a : 0.2f * a;
    float v = __expf(a);               // logits bounded: max-sub unnecessary
    int slot = c_doff[rel] + d;
    int pos = atomicAdd(&g_cnt[slot], 1);
    if (pos < BCAP)
        g_ent[(size_t)slot * BCAP + pos] = make_uint2((unsigned)s, __float_as_uint(v));
}

// ---------------- K6: per-node accumulation, MLP-4 batched gather ----------------
__global__ void k_accum(float* __restrict__ out, const float* __restrict__ bias) {
    int gw   = (blockIdx.x * blockDim.x + threadIdx.x) >> 5;
    int lane = threadIdx.x & 31;
    if (gw >= XROWS) return;
    int ty, d;
    if (gw < NP)           { ty = 0; d = gw; }
    else if (gw < NP + NL) { ty = 1; d = gw - NP; }
    else                   { ty = 2; d = gw - NP - NL; }

    float acc0 = 0.f, acc1 = 0.f, acc2 = 0.f, acc3 = 0.f;
    float4 bsum = make_float4(0.f, 0.f, 0.f, 0.f);

    #pragma unroll
    for (int q = 0; q < 3; q++) {
        int r = c_rel3[ty][q];
        float4 bv = *(const float4*)(bias + r * DOUT + lane * 4);
        bsum.x += bv.x; bsum.y += bv.y; bsum.z += bv.z; bsum.w += bv.w;

        int slot = c_doff[r] + d;
        int cnt = g_cnt[slot]; if (cnt > BCAP) cnt = BCAP;
        if (cnt == 0) continue;
        const uint2* lst = g_ent + (size_t)slot * BCAP;
        float den = 0.f;
        for (int j = 0; j < cnt; j++) den += __uint_as_float(lst[j].y);
        float inv = 1.f / den;
        const __half* Hb = g_H + (size_t)c_soff[r] * DOUT;

        // batched gather: 4 independent H-row loads in flight (MLP=4)
        for (int j = 0; j < cnt; j += 4) {
            uint2 en[4];
            #pragma unroll
            for (int t = 0; t < 4; t++)
                en[t] = (j + t < cnt) ? lst[j + t] : make_uint2(lst[j].x, 0u);
            uint2 u[4];
            #pragma unroll
            for (int t = 0; t < 4; t++)
                u[t] = *(const uint2*)(Hb + (size_t)en[t].x * DOUT + lane * 4);
            #pragma unroll
            for (int t = 0; t < 4; t++) {
                float wt = __uint_as_float(en[t].y) * inv;
                float2 f0 = __half22float2(*(__half2*)&u[t].x);
                float2 f1 = __half22float2(*(__half2*)&u[t].y);
                acc0 = fmaf(f0.x, wt, acc0);
                acc1 = fmaf(f0.y, wt, acc1);
                acc2 = fmaf(f1.x, wt, acc2);
                acc3 = fmaf(f1.y, wt, acc3);
            }
        }
    }

    float4 o;
    o.x = (acc0 + bsum.x) * (1.0f / 3.0f);
    o.y = (acc1 + bsum.y) * (1.0f / 3.0f);
    o.z = (acc2 + bsum.z) * (1.0f / 3.0f);
    o.w = (acc3 + bsum.w) * (1.0f / 3.0f);
    o.x = o.x > 0.f ? o.x : 0.f;
    o.y = o.y > 0.f ? o.y : 0.f;
    o.z = o.z > 0.f ? o.z : 0.f;
    o.w = o.w > 0.f ? o.w : 0.f;
    *(float4*)(out + (size_t)gw * DOUT + lane * 4) = o;
}

// ---------------- launch ----------------
extern "C" void kernel_launch(void* const* d_in, const int* in_sizes, int n_in,
                              void* d_out, int out_size) {
    const float* X[3] = {(const float*)d_in[0], (const float*)d_in[1], (const float*)d_in[2]};
    EdgePtrs ep;
    for (int r = 0; r < 9; r++) ep.ei[r] = (const int*)d_in[3 + r];
    const float* W    = (const float*)d_in[12];
    const float* as_  = (const float*)d_in[13];
    const float* ad_  = (const float*)d_in[14];
    const float* bias = (const float*)d_in[15];
    float* out = (float*)d_out;

    cudaFuncSetAttribute(k_mma_gemm, cudaFuncAttributeMaxDynamicSharedMemorySize, GE_SMEM);

    // init cursors + logit accumulators
    k_zero_cnt<<<(TOTROWS + 255) / 256, 256>>>();

    // conversions
    k_cvt_x<<<(NP * 128 + 255) / 256, 256>>>((const float4*)X[0], NP * 128, 0LL);
    k_cvt_x<<<(NL * 128 + 255) / 256, 256>>>((const float4*)X[1], NL * 128, (long long)NP * 128);
    k_cvt_x<<<(NG * 128 + 255) / 256, 256>>>((const float4*)X[2], NG * 128, (long long)(NP + NL) * 128);
    k_cvt_w<<<(9 * DIN * DOUT + 255) / 256, 256>>>(W);

    // dst attention matvec precompute + cross-type dst logits (fp32 X)
    k_wv<<<(9 * DIN + 255) / 256, 256>>>(W, ad_);
    k_node_dots2<<<(NP * 32 + 255) / 256, 256>>>(X[0], NP, 4, 310000, 7, 510000);
    k_node_dots2<<<(NL * 32 + 255) / 256, 256>>>(X[1], NL, 1, 100000, 8, 610000);
    k_node_dots2<<<(NG * 32 + 255) / 256, 256>>>(X[2], NG, 2, 180000, 5, 410000);

    // projections H[r] = X[src(r)] @ W[r]  (+ fused ssrc / same-type sdst)
    for (int r = 0; r < 9; r++) {
        int M = NTY[SRC_T[r]];
        k_mma_gemm<<<(M + 127) / 128, 256, GE_SMEM>>>(XOFF3[SRC_T[r]], M, r, SOFF[r],
                                                      as_, ad_, DOFF9[r], SAME9[r]);
    }

    // bucket fill (consumes ssrc/sdst)
    k_fill<<<9 * EBPR, 256>>>(ep);

    // per-node softmax + gather + mean + bias + relu
    k_accum<<<(XROWS * 32 + 255) / 256, 256>>>(out, bias);
}